// round 5
// baseline (speedup 1.0000x reference)
#include <cuda_runtime.h>
#include <cuda_fp16.h>
#include <math.h>

#define BATCH   1024
#define N_IN    1024
#define NLAYERS 5
#define NPL     2048
#define FANIN   16
#define N_OUT   256
#define W_ROWS  (N_IN + 4 * NPL)   // 9216 rows; layer-4 outputs go straight to d_out
#define NBLK    512                // 4 blocks/SM * 148 SMs = 592 >= 512 -> co-resident
#define ROW_BYTES (BATCH * 2)      // 2048 bytes per fp16 row

// Transposed fp16 value buffer: valsT[row, batch]. 18.9 MB, L2-resident, write-once rows.
__device__ __half g_vals[(size_t)W_ROWS * BATCH];
__device__ unsigned g_bar;

__device__ __forceinline__ float tanh_approx(float x) {
    float y;
    asm("tanh.approx.f32 %0, %1;" : "=f"(y) : "f"(x));
    return y;
}

__global__ void reset_kernel() { g_bar = 0u; }

// Grid-wide barrier: all NBLK blocks are co-resident by construction.
__device__ __forceinline__ void grid_barrier(unsigned target) {
    __syncthreads();                      // block done with phase work
    if (threadIdx.x == 0) {
        __threadfence();                  // release my writes
        atomicAdd(&g_bar, 1u);
        while (*(volatile unsigned*)&g_bar < target) {
            __nanosleep(64);
        }
        __threadfence();                  // acquire
    }
    __syncthreads();
}

// ---------------------------------------------------------------------------
// One fused kernel: transpose -> 4 hidden layers -> final layer.
// Block = 256 threads. Layer pass: 2 nodes (half = tid>>7) x 128 threads x
// 8 batch elems (one LDG.128 per fanin). Exactly 2 passes/block/layer.
// ---------------------------------------------------------------------------
__global__ void __launch_bounds__(256, 4) fused_kernel(
    const float* __restrict__ in,        // [B, N_IN]
    const int*   __restrict__ edge_src,  // [L, NPL, FANIN]
    const float* __restrict__ edge_w,    // [L, NPL, FANIN]
    const float* __restrict__ biases,    // [L, NPL]
    float*       __restrict__ out)       // [B, N_OUT]
{
    const int bid = blockIdx.x;
    __shared__ float tile[32][33];

    // ---- Phase 0: transpose input [B,N_IN] f32 -> g_vals[N_IN,B] f16 (2 tiles) ----
    {
        const int tx = threadIdx.x & 31;
        const int ty = threadIdx.x >> 5;      // 0..7
#pragma unroll 1
        for (int p = 0; p < 2; p++) {
            int tileid = bid + p * NBLK;      // 0..1023
            int bx = (tileid & 31) * 32;      // column tile
            int by = (tileid >> 5) * 32;      // batch tile
#pragma unroll
            for (int j = 0; j < 32; j += 8)
                tile[ty + j][tx] = in[(size_t)(by + ty + j) * N_IN + bx + tx];
            __syncthreads();
#pragma unroll
            for (int j = 0; j < 32; j += 8)
                g_vals[(size_t)(bx + ty + j) * BATCH + by + tx] =
                    __float2half_rn(tile[tx][ty + j]);
            __syncthreads();
        }
    }
    grid_barrier(NBLK);

    // ---- Phases 1..4: hidden layers ----
    const int  half = threadIdx.x >> 7;       // node slot within block
    const int  t    = threadIdx.x & 127;      // owns batch [t*8, t*8+8)
    const unsigned toff = (unsigned)t * 16u;  // byte offset within a row
    const char* gbase = (const char*)g_vals;

#pragma unroll 1
    for (int l = 0; l < NLAYERS - 1; l++) {
        const int*   src = edge_src + l * NPL * FANIN;
        const float* wgt = edge_w   + l * NPL * FANIN;
        const float* bia = biases   + l * NPL;
        const int    base = N_IN + l * NPL;

#pragma unroll 1
        for (int p = 0; p < 2; p++) {
            const int n = (bid + p * NBLK) * 2 + half;   // 0..2047

            int   sidx[FANIN];
            float wv[FANIN];
            {
                const int4*   s4 = (const int4*)(src + n * FANIN);
                const float4* w4 = (const float4*)(wgt + n * FANIN);
#pragma unroll
                for (int q = 0; q < FANIN / 4; q++) {
                    int4   si = __ldg(s4 + q);
                    float4 wi = __ldg(w4 + q);
                    sidx[q*4+0] = si.x; sidx[q*4+1] = si.y;
                    sidx[q*4+2] = si.z; sidx[q*4+3] = si.w;
                    wv[q*4+0] = wi.x; wv[q*4+1] = wi.y;
                    wv[q*4+2] = wi.z; wv[q*4+3] = wi.w;
                }
            }

            float bv = __ldg(bia + n);
            float acc[8];
#pragma unroll
            for (int i = 0; i < 8; i++) acc[i] = bv;

#pragma unroll
            for (int f = 0; f < FANIN; f++) {
                unsigned off = (unsigned)sidx[f] * (unsigned)ROW_BYTES + toff;
                uint4 v = *(const uint4*)(gbase + off);
                float wf = wv[f];
                float2 f0 = __half22float2(*(__half2*)&v.x);
                float2 f1 = __half22float2(*(__half2*)&v.y);
                float2 f2 = __half22float2(*(__half2*)&v.z);
                float2 f3 = __half22float2(*(__half2*)&v.w);
                acc[0] = fmaf(wf, f0.x, acc[0]);
                acc[1] = fmaf(wf, f0.y, acc[1]);
                acc[2] = fmaf(wf, f1.x, acc[2]);
                acc[3] = fmaf(wf, f1.y, acc[3]);
                acc[4] = fmaf(wf, f2.x, acc[4]);
                acc[5] = fmaf(wf, f2.y, acc[5]);
                acc[6] = fmaf(wf, f3.x, acc[6]);
                acc[7] = fmaf(wf, f3.y, acc[7]);
            }

#pragma unroll
            for (int i = 0; i < 8; i++) acc[i] = tanh_approx(acc[i]);

            uint4 o;
            *(__half2*)&o.x = __floats2half2_rn(acc[0], acc[1]);
            *(__half2*)&o.y = __floats2half2_rn(acc[2], acc[3]);
            *(__half2*)&o.z = __floats2half2_rn(acc[4], acc[5]);
            *(__half2*)&o.w = __floats2half2_rn(acc[6], acc[7]);
            *(uint4*)&g_vals[(size_t)(base + n) * BATCH + t * 8] = o;
        }
        grid_barrier((unsigned)NBLK * (l + 2));
    }

    // ---- Phase 5: final layer (last N_OUT nodes), sigmoid, f32 out ----
    if (bid < N_OUT / 2) {
        const int j = bid * 2 + half;             // 0..N_OUT-1
        const int n = NPL - N_OUT + j;
        const int lf = NLAYERS - 1;
        const int*   src = edge_src + lf * NPL * FANIN;
        const float* wgt = edge_w   + lf * NPL * FANIN;
        const float* bia = biases   + lf * NPL;

        int   sidx[FANIN];
        float wv[FANIN];
        {
            const int4*   s4 = (const int4*)(src + n * FANIN);
            const float4* w4 = (const float4*)(wgt + n * FANIN);
#pragma unroll
            for (int q = 0; q < FANIN / 4; q++) {
                int4   si = __ldg(s4 + q);
                float4 wi = __ldg(w4 + q);
                sidx[q*4+0] = si.x; sidx[q*4+1] = si.y;
                sidx[q*4+2] = si.z; sidx[q*4+3] = si.w;
                wv[q*4+0] = wi.x; wv[q*4+1] = wi.y;
                wv[q*4+2] = wi.z; wv[q*4+3] = wi.w;
            }
        }

        float bv = __ldg(bia + n);
        float acc[8];
#pragma unroll
        for (int i = 0; i < 8; i++) acc[i] = bv;

#pragma unroll
        for (int f = 0; f < FANIN; f++) {
            unsigned off = (unsigned)sidx[f] * (unsigned)ROW_BYTES + toff;
            uint4 v = *(const uint4*)(gbase + off);
            float wf = wv[f];
            float2 f0 = __half22float2(*(__half2*)&v.x);
            float2 f1 = __half22float2(*(__half2*)&v.y);
            float2 f2 = __half22float2(*(__half2*)&v.z);
            float2 f3 = __half22float2(*(__half2*)&v.w);
            acc[0] = fmaf(wf, f0.x, acc[0]);
            acc[1] = fmaf(wf, f0.y, acc[1]);
            acc[2] = fmaf(wf, f1.x, acc[2]);
            acc[3] = fmaf(wf, f1.y, acc[3]);
            acc[4] = fmaf(wf, f2.x, acc[4]);
            acc[5] = fmaf(wf, f2.y, acc[5]);
            acc[6] = fmaf(wf, f3.x, acc[6]);
            acc[7] = fmaf(wf, f3.y, acc[7]);
        }

        const int b = t * 8;
#pragma unroll
        for (int i = 0; i < 8; i++) {
            float s = 1.0f / (1.0f + expf(-acc[i]));
            out[(size_t)(b + i) * N_OUT + j] = s;
        }
    }
}

// ---------------------------------------------------------------------------
extern "C" void kernel_launch(void* const* d_in, const int* in_sizes, int n_in,
                              void* d_out, int out_size) {
    const float* inputs   = (const float*)d_in[0];
    const int*   edge_src = (const int*)  d_in[1];
    const float* edge_w   = (const float*)d_in[2];
    const float* biases   = (const float*)d_in[3];
    float*       out      = (float*)d_out;

    reset_kernel<<<1, 1>>>();
    fused_kernel<<<NBLK, 256>>>(inputs, edge_src, edge_w, biases, out);
}